// round 17
// baseline (speedup 1.0000x reference)
#include <cuda_runtime.h>
#include <math.h>

#define N_NODES 20000
#define N_EDGES 320000
#define D 128
#define H 8
#define G 64
#define LN_EPS 1e-5f
#define WMAXD 64

#define WIDTH   (5.0f / 63.0f)
#define INV_W   (63.0f / 5.0f)
#define EXP_COEF (-0.5f * INV_W * INV_W)
#define PI_OVER_CUT 0.62831853071795864f
#define INV_SQRT_P 0.25f

// ---------------- scratch ----------------
static __device__ __align__(16) float g_q[(size_t)N_EDGES * D];     // SORTED by src
static __device__ float g_C[N_EDGES];                               // SORTED by src
static __device__ __align__(16) float g_gk[(size_t)N_NODES * H * D];
static __device__ __align__(16) float g_h2[(size_t)N_NODES * D];
static __device__ int g_hist[N_NODES];
static __device__ int g_off[N_NODES + 1];
static __device__ int g_cursor[N_NODES];
static __device__ int g_pos[N_EDGES];
static __device__ int g_done;

// ---------------- KA: fused histogram + scan (one launch, spin barrier) ----------------
__global__ void __launch_bounds__(256) ka_histscan(const int* __restrict__ src) {
    for (int e = blockIdx.x * blockDim.x + threadIdx.x; e < N_EDGES;
         e += gridDim.x * blockDim.x)
        atomicAdd(&g_hist[src[e]], 1);
    __threadfence();
    __syncthreads();
    if (threadIdx.x == 0) atomicAdd(&g_done, 1);

    if (blockIdx.x != 0) return;
    if (threadIdx.x == 0) {
        while (*((volatile int*)&g_done) < (int)gridDim.x) { }
    }
    __syncthreads();
    __threadfence();

    __shared__ int sh[256];
    const int tid = threadIdx.x;
    const int CH = (N_NODES + 255) / 256;
    const int lo = tid * CH;
    const int hi = min(lo + CH, N_NODES);
    int s = 0;
    for (int i = lo; i < hi; i++) s += g_hist[i];
    sh[tid] = s;
    __syncthreads();
    for (int off = 1; off < 256; off <<= 1) {
        int v = (tid >= off) ? sh[tid - off] : 0;
        __syncthreads();
        sh[tid] += v;
        __syncthreads();
    }
    int base = (tid == 0) ? 0 : sh[tid - 1];
    for (int i = lo; i < hi; i++) {
        int c = g_hist[i];
        g_off[i] = base;
        g_cursor[i] = base;
        g_hist[i] = 0;
        base += c;
    }
    __syncthreads();
    if (tid == 0) { g_off[N_NODES] = N_EDGES; g_done = 0; }
}

// ---------------- K1: warp-per-edge; colsum folded; 3-shfl scalar broadcast ----------------
__global__ void __launch_bounds__(256) k1_edge(
    const float* __restrict__ pos, const float* __restrict__ h1,
    const float* __restrict__ t,   const float* __restrict__ fw,
    const float* __restrict__ fb,  const float* __restrict__ ln_g,
    const float* __restrict__ ln_b,const int* __restrict__ src,
    const int* __restrict__ dst,   float* __restrict__ outW)
{
    __shared__ float4 sh_fw[G * 32];
    const int tid  = threadIdx.x;
    const int lane = tid & 31;
    const int w    = tid >> 5;               // 0..7
    const unsigned FULL = 0xffffffffu;

    for (int i = tid; i < G * 32; i += 256) sh_fw[i] = ((const float4*)fw)[i];
    __syncthreads();

    float4 fbc4;
    {
        float4 cs = make_float4(0.f, 0.f, 0.f, 0.f);
        #pragma unroll
        for (int g = 0; g < G; g++) {
            const float4 w4 = sh_fw[g * 32 + lane];
            cs.x += w4.x; cs.y += w4.y; cs.z += w4.z; cs.w += w4.w;
        }
        const float4 fb4 = ((const float4*)fb)[lane];
        fbc4.x = fb4.x - cs.x; fbc4.y = fb4.y - cs.y;
        fbc4.z = fb4.z - cs.z; fbc4.w = fb4.w - cs.w;
    }
    const float4 lg4 = ((const float4*)ln_g)[lane];
    const float4 lb4 = ((const float4*)ln_b)[lane];

    const int e0 = blockIdx.x * 128 + w * 16;

    int dn_me = 0, p_me = 0;
    float r_me = 0.f, C_me = 0.f;
    if (lane < 16) {
        const int e = e0 + lane;
        const int s = src[e];
        dn_me = dst[e];
        const float dx = pos[dn_me*3+0] - pos[s*3+0];
        const float dy = pos[dn_me*3+1] - pos[s*3+1];
        const float dz = pos[dn_me*3+2] - pos[s*3+2];
        r_me = sqrtf(dx*dx + dy*dy + dz*dz);
        C_me = (r_me < 5.0f) ? 0.5f * (__cosf(r_me * PI_OVER_CUT) + 1.0f) : 0.0f;
        p_me = atomicAdd(&g_cursor[s], 1);
        g_pos[e] = p_me;
        g_C[p_me] = C_me;
    }

    int dn_nx = __shfl_sync(FULL, dn_me, 0);
    float4 h4n = ((const float4*)h1)[(size_t)dn_nx * 32 + lane];
    float4 t4n = ((const float4*)t)[(size_t)e0 * 32 + lane];

    #pragma unroll 1
    for (int ei = 0; ei < 16; ei++) {
        const int e = e0 + ei;
        const float4 h4 = h4n;
        const float4 t4 = t4n;
        if (ei + 1 < 16) {
            dn_nx = __shfl_sync(FULL, dn_me, ei + 1);
            h4n = ((const float4*)h1)[(size_t)dn_nx * 32 + lane];
            t4n = ((const float4*)t)[(size_t)(e + 1) * 32 + lane];
        }
        const int   p_e = __shfl_sync(FULL, p_me, ei);
        const float C_e = __shfl_sync(FULL, C_me, ei);
        const float r_e = __shfl_sync(FULL, r_me, ei);
        const int i0_e  = __float2int_rn(r_e * INV_W);
        const int glo_e = max(0, i0_e - 4);
        const int ghi_e = min(G - 1, i0_e + 4);
        const int nwin_e = ghi_e - glo_e + 1;     // <= 9

        float myf = 0.f;
        if (lane < nwin_e) {
            const float dr = r_e - (glo_e + lane) * WIDTH;
            myf = __expf(EXP_COEF * dr * dr);
        }

        float4 acc = make_float4(0.f, 0.f, 0.f, 0.f);
        for (int j = 0; j < nwin_e; j++) {
            const float fj = __shfl_sync(FULL, myf, j);
            const float4 w4 = sh_fw[(glo_e + j) * 32 + lane];
            acc.x += fj * w4.x; acc.y += fj * w4.y;
            acc.z += fj * w4.z; acc.w += fj * w4.w;
        }
        float4 W4;
        W4.x = (2.0f * acc.x + fbc4.x) * C_e;
        W4.y = (2.0f * acc.y + fbc4.y) * C_e;
        W4.z = (2.0f * acc.z + fbc4.z) * C_e;
        W4.w = (2.0f * acc.w + fbc4.w) * C_e;
        ((float4*)outW)[(size_t)e * 32 + lane] = W4;

        float4 v;
        v.x = W4.x * h4.x + t4.x; v.y = W4.y * h4.y + t4.y;
        v.z = W4.z * h4.z + t4.z; v.w = W4.w * h4.w + t4.w;

        float sm = v.x + v.y + v.z + v.w;
        float sq = v.x*v.x + v.y*v.y + v.z*v.z + v.w*v.w;
        #pragma unroll
        for (int o = 16; o; o >>= 1) {
            sm += __shfl_xor_sync(FULL, sm, o);
            sq += __shfl_xor_sync(FULL, sq, o);
        }
        const float mu  = sm * (1.0f / D);
        const float var = sq * (1.0f / D) - mu * mu;
        const float inv = rsqrtf(var + LN_EPS);
        float4 qo;
        qo.x = (v.x - mu) * inv * lg4.x + lb4.x;
        qo.y = (v.y - mu) * inv * lg4.y + lb4.y;
        qo.z = (v.z - mu) * inv * lg4.z + lb4.z;
        qo.w = (v.w - mu) * inv * lg4.w + lb4.w;
        ((float4*)g_q)[(size_t)p_e * 32 + lane] = qo;
    }
}

// ---------------- K45: 512 threads, 64-node tiles; gk phase 4-node register-blocked ----------------
__global__ void __launch_bounds__(512) k45_gk(
    const float* __restrict__ Wq, const float* __restrict__ Wk,
    const int* __restrict__ q_id)
{
    extern __shared__ float sm[];
    float* shWq  = sm;                    // 16384
    float* shWkT = shWq + 16384;          // 128*132 = 16896
    float* shq   = shWkT + 16896;         // 8192
    float* shqv  = shq + 8192;            // 8192
    int*   shIdx = (int*)(shqv + 8192);   // 64
    const int tid = threadIdx.x;
    const int tx = tid & 31, ty = tid >> 5;      // ty 0..15

    for (int i = tid; i < D * D; i += 512) shWq[i] = Wq[i];
    for (int i = tid; i < D * D; i += 512) {
        const int d = i >> 7, j = i & 127;
        shWkT[j * 132 + d] = Wk[i];
    }
    const float4* wrow = (const float4*)shWkT;   // row stride 33 float4

    const int NT = (N_NODES + 63) / 64;          // 313
    for (int tile = blockIdx.x; tile < NT; tile += gridDim.x) {
        const int n0 = tile * 64;
        __syncthreads();
        if (tid < 64) {
            const int nn = n0 + tid;
            shIdx[tid] = g_pos[q_id[(nn < N_NODES) ? nn : 0]];
        }
        __syncthreads();
        for (int i = tid; i < 2048; i += 512)
            ((float4*)shq)[i] = ((const float4*)g_q)[(size_t)shIdx[i >> 5] * 32 + (i & 31)];
        __syncthreads();

        {   // qv = shq @ Wq
            float4 a0 = make_float4(0,0,0,0), a1 = a0, a2 = a0, a3 = a0;
            const float* q0 = shq + (ty * 4) * D;
            #pragma unroll 4
            for (int k = 0; k < D; k++) {
                const float4 wv = ((const float4*)shWq)[k * 32 + tx];
                const float b0 = q0[k], b1 = q0[D + k], b2 = q0[2*D + k], b3 = q0[3*D + k];
                a0.x += b0*wv.x; a0.y += b0*wv.y; a0.z += b0*wv.z; a0.w += b0*wv.w;
                a1.x += b1*wv.x; a1.y += b1*wv.y; a1.z += b1*wv.z; a1.w += b1*wv.w;
                a2.x += b2*wv.x; a2.y += b2*wv.y; a2.z += b2*wv.z; a2.w += b2*wv.w;
                a3.x += b3*wv.x; a3.y += b3*wv.y; a3.z += b3*wv.z; a3.w += b3*wv.w;
            }
            ((float4*)shqv)[(ty*4 + 0) * 32 + tx] = a0;
            ((float4*)shqv)[(ty*4 + 1) * 32 + tx] = a1;
            ((float4*)shqv)[(ty*4 + 2) * 32 + tx] = a2;
            ((float4*)shqv)[(ty*4 + 3) * 32 + tx] = a3;
        }
        __syncthreads();

        {   // gk phase: warp ty -> head (ty&7), node-half (ty>>3); 4 nodes per pass
            const int h = ty & 7, half = ty >> 3, c = tx;
            const int wbase = h * 16;
            #pragma unroll 1
            for (int n = 0; n < 32; n += 4) {
                const int nn = half * 32 + n;
                const float* q0 = shqv + nn * D + wbase;
                const float* q1 = q0 + D;
                const float* q2 = q0 + 2 * D;
                const float* q3 = q0 + 3 * D;
                float4 c0 = make_float4(0,0,0,0), c1 = c0, c2 = c0, c3 = c0;
                #pragma unroll
                for (int p4 = 0; p4 < 4; p4++) {
                    const float4 a0 = *(const float4*)&q0[p4 * 4];
                    const float4 a1 = *(const float4*)&q1[p4 * 4];
                    const float4 a2 = *(const float4*)&q2[p4 * 4];
                    const float4 a3 = *(const float4*)&q3[p4 * 4];
                    const float4 w0 = wrow[(wbase + p4*4 + 0) * 33 + c];
                    const float4 w1 = wrow[(wbase + p4*4 + 1) * 33 + c];
                    const float4 w2 = wrow[(wbase + p4*4 + 2) * 33 + c];
                    const float4 w3 = wrow[(wbase + p4*4 + 3) * 33 + c];
                    c0.x += a0.x*w0.x + a0.y*w1.x + a0.z*w2.x + a0.w*w3.x;
                    c0.y += a0.x*w0.y + a0.y*w1.y + a0.z*w2.y + a0.w*w3.y;
                    c0.z += a0.x*w0.z + a0.y*w1.z + a0.z*w2.z + a0.w*w3.z;
                    c0.w += a0.x*w0.w + a0.y*w1.w + a0.z*w2.w + a0.w*w3.w;
                    c1.x += a1.x*w0.x + a1.y*w1.x + a1.z*w2.x + a1.w*w3.x;
                    c1.y += a1.x*w0.y + a1.y*w1.y + a1.z*w2.y + a1.w*w3.y;
                    c1.z += a1.x*w0.z + a1.y*w1.z + a1.z*w2.z + a1.w*w3.z;
                    c1.w += a1.x*w0.w + a1.y*w1.w + a1.z*w2.w + a1.w*w3.w;
                    c2.x += a2.x*w0.x + a2.y*w1.x + a2.z*w2.x + a2.w*w3.x;
                    c2.y += a2.x*w0.y + a2.y*w1.y + a2.z*w2.y + a2.w*w3.y;
                    c2.z += a2.x*w0.z + a2.y*w1.z + a2.z*w2.z + a2.w*w3.z;
                    c2.w += a2.x*w0.w + a2.y*w1.w + a2.z*w2.w + a2.w*w3.w;
                    c3.x += a3.x*w0.x + a3.y*w1.x + a3.z*w2.x + a3.w*w3.x;
                    c3.y += a3.x*w0.y + a3.y*w1.y + a3.z*w2.y + a3.w*w3.y;
                    c3.z += a3.x*w0.z + a3.y*w1.z + a3.z*w2.z + a3.w*w3.z;
                    c3.w += a3.x*w0.w + a3.y*w1.w + a3.z*w2.w + a3.w*w3.w;
                }
                const int gn = n0 + nn;
                if (gn + 0 < N_NODES) ((float4*)g_gk)[((size_t)(gn+0) * H + h) * 32 + c] = c0;
                if (gn + 1 < N_NODES) ((float4*)g_gk)[((size_t)(gn+1) * H + h) * 32 + c] = c1;
                if (gn + 2 < N_NODES) ((float4*)g_gk)[((size_t)(gn+2) * H + h) * 32 + c] = c2;
                if (gn + 3 < N_NODES) ((float4*)g_gk)[((size_t)(gn+3) * H + h) * 32 + c] = c3;
            }
        }
    }
}

// ---------------- K7: WARP-PER-NODE, single-pass, 2-EDGE-BATCHED reduction tree ----------------
// Per pair of edges: 16 (edge,head) dots reduced with one 31-shfl tree;
// lane ends with x = logit(edge = bit4, head = (lane>>1)&7). Odd deg padded with C=0.
__global__ void __launch_bounds__(256, 2) k7_node(const float* __restrict__ Wv) {
    extern __shared__ float sm[];
    float* shWv  = sm;                  // 16384 (64 KB)
    float* shBuf = shWv + 16384;        // 8 * 1024  per-warp Y staging
    float* shCb  = shBuf + 8192;        // 8 * 64    per-warp C

    const int tid  = threadIdx.x;
    const int lane = tid & 31;
    const int w    = tid >> 5;
    const unsigned FULL = 0xffffffffu;
    float* myL = shBuf + w * 1024;
    float* myC = shCb + w * WMAXD;

    for (int i = tid; i < D * D; i += 256) shWv[i] = Wv[i];
    __syncthreads();

    for (int n = blockIdx.x * 8 + w; n < N_NODES; n += gridDim.x * 8) {
        const int base = g_off[n];
        const int deg  = g_off[n + 1] - base;
        if (deg == 0) {
            ((float4*)g_h2)[(size_t)n * 32 + lane] = make_float4(0,0,0,0);
            continue;
        }

        float4 g4[H];
        #pragma unroll
        for (int h = 0; h < H; h++)
            g4[h] = ((const float4*)g_gk)[((size_t)n * H + h) * 32 + lane];

        float4 Y[H];
        #pragma unroll
        for (int h = 0; h < H; h++) Y[h] = make_float4(0,0,0,0);

        if (deg <= WMAXD) {
            for (int j = lane; j < deg; j += 32) myC[j] = g_C[base + j];
            __syncwarp();

            float s_own = 0.f;
            // prefetch first pair (pad b with a copy of edge 0 when deg==1)
            float4 qa = ((const float4*)g_q)[(size_t)base * 32 + lane];
            float4 qb = qa;
            if (deg > 1) qb = ((const float4*)g_q)[(size_t)(base + 1) * 32 + lane];

            for (int i = 0; i < deg; i += 2) {
                const float4 q0 = qa, q1 = qb;
                const float C0 = myC[i];
                const float C1 = (i + 1 < deg) ? myC[i + 1] : 0.f;
                if (i + 2 < deg) {
                    qa = ((const float4*)g_q)[(size_t)(base + i + 2) * 32 + lane];
                    qb = (i + 3 < deg)
                       ? ((const float4*)g_q)[(size_t)(base + i + 3) * 32 + lane] : qa;
                }

                float pa[8], pb[8];
                #pragma unroll
                for (int h = 0; h < 8; h++) {
                    pa[h] = q0.x*g4[h].x + q0.y*g4[h].y + q0.z*g4[h].z + q0.w*g4[h].w;
                    pb[h] = q1.x*g4[h].x + q1.y*g4[h].y + q1.z*g4[h].z + q1.w*g4[h].w;
                }
                #pragma unroll
                for (int h = 0; h < 8; h++) {
                    pa[h] += __shfl_xor_sync(FULL, pa[h], 16);
                    pb[h] += __shfl_xor_sync(FULL, pb[h], 16);
                }
                float r[8];
                #pragma unroll
                for (int h = 0; h < 8; h++) r[h] = (lane & 16) ? pb[h] : pa[h];
                #pragma unroll
                for (int h = 0; h < 8; h++) r[h] += __shfl_xor_sync(FULL, r[h], 8);
                float u[4];
                #pragma unroll
                for (int j = 0; j < 4; j++) u[j] = (lane & 8) ? r[j + 4] : r[j];
                #pragma unroll
                for (int j = 0; j < 4; j++) u[j] += __shfl_xor_sync(FULL, u[j], 4);
                float v0 = (lane & 4) ? u[2] : u[0];
                float v1 = (lane & 4) ? u[3] : u[1];
                v0 += __shfl_xor_sync(FULL, v0, 2);
                v1 += __shfl_xor_sync(FULL, v1, 2);
                float x = (lane & 2) ? v1 : v0;
                x += __shfl_xor_sync(FULL, x, 1);
                // lane holds logit of (edge = bit4 ? i+1 : i, head = (lane>>1)&7)
                const float Ce = (lane & 16) ? C1 : C0;
                const float a = __expf(x * INV_SQRT_P) * Ce;
                s_own += a;
                #pragma unroll
                for (int h = 0; h < 8; h++) {
                    const float aa = __shfl_sync(FULL, a, 2 * h);
                    const float ab = __shfl_sync(FULL, a, 2 * h + 16);
                    Y[h].x += aa * q0.x + ab * q1.x;
                    Y[h].y += aa * q0.y + ab * q1.y;
                    Y[h].z += aa * q0.z + ab * q1.z;
                    Y[h].w += aa * q0.w + ab * q1.w;
                }
            }
            // combine per-parity sums; rs valid for head (lane>>1)&7 at every lane
            const float stot = s_own + __shfl_xor_sync(FULL, s_own, 16);
            const float rs = 1.0f / stot;
            #pragma unroll
            for (int h = 0; h < H; h++) {
                const float si = __shfl_sync(FULL, rs, 2 * h);
                Y[h].x *= si; Y[h].y *= si; Y[h].z *= si; Y[h].w *= si;
                *(float4*)&myL[h * D + lane * 4] = Y[h];
            }
            __syncwarp();
        } else {
            // ---- fallback: warp-local flash online softmax (rare) ----
            float m[H], s[H];
            #pragma unroll
            for (int h = 0; h < H; h++) { m[h] = -1e30f; s[h] = 0.f; }
            for (int i = 0; i < deg; i++) {
                const float4 q4 = ((const float4*)g_q)[(size_t)(base + i) * 32 + lane];
                const float Ce = g_C[base + i];
                #pragma unroll
                for (int h = 0; h < H; h++) {
                    float pq = q4.x*g4[h].x + q4.y*g4[h].y + q4.z*g4[h].z + q4.w*g4[h].w;
                    #pragma unroll
                    for (int o = 16; o; o >>= 1) pq += __shfl_xor_sync(FULL, pq, o);
                    pq *= INV_SQRT_P;
                    const float nm = fmaxf(m[h], pq);
                    const float sc = __expf(m[h] - nm);
                    const float ww = __expf(pq - nm) * Ce;
                    s[h] = s[h] * sc + ww;
                    Y[h].x = Y[h].x * sc + ww * q4.x;
                    Y[h].y = Y[h].y * sc + ww * q4.y;
                    Y[h].z = Y[h].z * sc + ww * q4.z;
                    Y[h].w = Y[h].w * sc + ww * q4.w;
                    m[h] = nm;
                }
            }
            #pragma unroll
            for (int h = 0; h < H; h++) {
                const float si = 1.0f / s[h];
                Y[h].x *= si; Y[h].y *= si; Y[h].z *= si; Y[h].w *= si;
                *(float4*)&myL[h * D + lane * 4] = Y[h];
            }
            __syncwarp();
        }

        // ---- epilogue: h2[j] = sum_d Y[j>>4, d] * Wv[d, j] ----
        const float* yrow = myL + (lane >> 2) * D;
        float4 hv = make_float4(0,0,0,0);
        #pragma unroll 8
        for (int d = 0; d < D; d += 4) {
            const float4 y4 = *(const float4*)&yrow[d];
            const float4 w0 = ((const float4*)shWv)[(d+0) * 32 + lane];
            const float4 w1 = ((const float4*)shWv)[(d+1) * 32 + lane];
            const float4 w2 = ((const float4*)shWv)[(d+2) * 32 + lane];
            const float4 w3 = ((const float4*)shWv)[(d+3) * 32 + lane];
            hv.x += y4.x*w0.x + y4.y*w1.x + y4.z*w2.x + y4.w*w3.x;
            hv.y += y4.x*w0.y + y4.y*w1.y + y4.z*w2.y + y4.w*w3.y;
            hv.z += y4.x*w0.z + y4.y*w1.z + y4.z*w2.z + y4.w*w3.z;
            hv.w += y4.x*w0.w + y4.y*w1.w + y4.z*w2.w + y4.w*w3.w;
        }
        ((float4*)g_h2)[(size_t)n * 32 + lane] = hv;
    }
}

// ---------------- K8: tiled m_agg = h2 @ Wo ----------------
__global__ void __launch_bounds__(256) k8_out(const float* __restrict__ Wo,
                                              float* __restrict__ outM) {
    extern __shared__ float sm[];
    float* shW = sm;             // 16384
    float* shq = shW + 16384;    // 4096
    const int tid = threadIdx.x;
    const int tx = tid & 31, ty = tid >> 5;

    for (int i = tid; i < D * D; i += 256) shW[i] = Wo[i];

    for (int tile = blockIdx.x; tile < N_NODES / 32; tile += gridDim.x) {
        const int n0 = tile * 32;
        __syncthreads();
        for (int i = tid; i < 1024; i += 256)
            ((float4*)shq)[i] = ((const float4*)g_h2)[(size_t)n0 * 32 + i];
        __syncthreads();

        float4 a0 = make_float4(0,0,0,0), a1 = a0, a2 = a0, a3 = a0;
        const float* q0 = shq + (ty * 4) * D;
        #pragma unroll 4
        for (int k = 0; k < D; k++) {
            const float4 wv = ((const float4*)shW)[k * 32 + tx];
            const float b0 = q0[k], b1 = q0[D + k], b2 = q0[2*D + k], b3 = q0[3*D + k];
            a0.x += b0*wv.x; a0.y += b0*wv.y; a0.z += b0*wv.z; a0.w += b0*wv.w;
            a1.x += b1*wv.x; a1.y += b1*wv.y; a1.z += b1*wv.z; a1.w += b1*wv.w;
            a2.x += b2*wv.x; a2.y += b2*wv.y; a2.z += b2*wv.z; a2.w += b2*wv.w;
            a3.x += b3*wv.x; a3.y += b3*wv.y; a3.z += b3*wv.z; a3.w += b3*wv.w;
        }
        ((float4*)outM)[(size_t)(n0 + ty*4 + 0) * 32 + tx] = a0;
        ((float4*)outM)[(size_t)(n0 + ty*4 + 1) * 32 + tx] = a1;
        ((float4*)outM)[(size_t)(n0 + ty*4 + 2) * 32 + tx] = a2;
        ((float4*)outM)[(size_t)(n0 + ty*4 + 3) * 32 + tx] = a3;
    }
}

// ---------------- launch ----------------
extern "C" void kernel_launch(void* const* d_in, const int* in_sizes, int n_in,
                              void* d_out, int out_size) {
    const float* pos  = (const float*)d_in[0];
    const float* h1   = (const float*)d_in[1];
    const float* t    = (const float*)d_in[2];
    const float* fw   = (const float*)d_in[3];
    const float* fb   = (const float*)d_in[4];
    const float* ln_g = (const float*)d_in[5];
    const float* ln_b = (const float*)d_in[6];
    const float* Wq   = (const float*)d_in[7];
    const float* Wk   = (const float*)d_in[8];
    const float* Wv   = (const float*)d_in[9];
    const float* Wo   = (const float*)d_in[10];
    const int* src    = (const int*)d_in[11];
    const int* dst    = (const int*)d_in[12];
    const int* q_id   = (const int*)d_in[13];

    float* out  = (float*)d_out;
    float* outM = out;                              // m_agg [N,D]
    float* outW = out + (size_t)N_NODES * D;        // W     [E,D]

    const size_t sm_k45 = (16384 + 16896 + 8192 + 8192) * sizeof(float) + 64 * sizeof(int);
    const size_t sm_k7  = (16384 + 8192 + 512) * sizeof(float);       // 100,352 B (2 CTAs/SM)
    const size_t sm_k8  = (16384 + 4096) * sizeof(float);

    cudaFuncSetAttribute(k45_gk,  cudaFuncAttributeMaxDynamicSharedMemorySize, (int)sm_k45);
    cudaFuncSetAttribute(k7_node, cudaFuncAttributeMaxDynamicSharedMemorySize, (int)sm_k7);
    cudaFuncSetAttribute(k8_out,  cudaFuncAttributeMaxDynamicSharedMemorySize, (int)sm_k8);

    ka_histscan<<<148, 256>>>(src);                                   // 0
    k1_edge<<<N_EDGES / 128, 256>>>(pos, h1, t, fw, fb, ln_g, ln_b,
                                    src, dst, outW);                  // 1
    k45_gk<<<148, 512, sm_k45>>>(Wq, Wk, q_id);                       // 2
    k7_node<<<296, 256, sm_k7>>>(Wv);                                 // 3  <-- profiled
    k8_out<<<296, 256, sm_k8>>>(Wo, outM);                            // 4
}